// round 1
// baseline (speedup 1.0000x reference)
#include <cuda_runtime.h>
#include <math.h>

// ---------------- problem constants (fixed shapes) ----------------
#define NT 10000      // total nodes (4*2500)
#define NE 120000     // edges
#define HCMAX 512     // max hidden width (4 heads * 128)

// ---------------- device scratch (no allocations allowed) ----------------
__device__ float g_XL[NT * HCMAX];   // source transform  x@Wl+bl
__device__ float g_XR[NT * HCMAX];   // target transform  x@Wr+br
__device__ float g_H [NT * HCMAX];   // layer activations
__device__ int   g_deg[NT];
__device__ int   g_start[NT + 1];
__device__ int   g_cursor[NT];
__device__ int   g_csr[NE];          // edge ids grouped by dst

// ---------------- CSR build ----------------
__global__ void k_zero_deg() {
    int i = blockIdx.x * blockDim.x + threadIdx.x;
    if (i < NT) g_deg[i] = 0;
}

__global__ void k_hist(const int* __restrict__ dst) {
    int e = blockIdx.x * blockDim.x + threadIdx.x;
    if (e < NE) atomicAdd(&g_deg[dst[e]], 1);
}

__global__ void k_scan() {
    // single block, 256 threads, chunk of 40 nodes each
    __shared__ int sh[256];
    const int CH = (NT + 255) / 256;  // 40
    int tid = threadIdx.x;
    int base = tid * CH;
    int s = 0;
    for (int i = 0; i < CH; i++) {
        int n = base + i;
        if (n < NT) s += g_deg[n];
    }
    sh[tid] = s;
    __syncthreads();
    // Hillis-Steele inclusive scan over 256 partials
    for (int off = 1; off < 256; off <<= 1) {
        int v = (tid >= off) ? sh[tid - off] : 0;
        __syncthreads();
        sh[tid] += v;
        __syncthreads();
    }
    int run = sh[tid] - s;   // exclusive prefix of this chunk
    for (int i = 0; i < CH; i++) {
        int n = base + i;
        if (n < NT) {
            g_start[n]  = run;
            g_cursor[n] = run;
            run += g_deg[n];
        }
    }
    if (tid == 255) g_start[NT] = sh[255];
}

__global__ void k_scatter(const int* __restrict__ dst) {
    int e = blockIdx.x * blockDim.x + threadIdx.x;
    if (e < NE) {
        int p = atomicAdd(&g_cursor[dst[e]], 1);
        g_csr[p] = e;
    }
}

// ---------------- dual GEMM:  C0 = A@B0+bias0,  C1 = A@B1+bias1 ----------------
// 64x64 tile, BK=16, 256 threads, 4x4 micro-tile per thread. blockIdx.z selects (B0,C0)/(B1,C1).
__global__ void __launch_bounds__(256)
k_gemm_dual(const float* __restrict__ A,
            const float* __restrict__ B0, const float* __restrict__ bias0, float* __restrict__ C0,
            const float* __restrict__ B1, const float* __restrict__ bias1, float* __restrict__ C1,
            int M, int N, int K) {
    constexpr int BM = 64, BN = 64, BK = 16;
    const float* B    = blockIdx.z ? B1    : B0;
    const float* bias = blockIdx.z ? bias1 : bias0;
    float*       C    = blockIdx.z ? C1    : C0;

    __shared__ float As[BK][BM];
    __shared__ float Bs[BK][BN];

    int tid = threadIdx.x;
    int tx = tid & 15;        // 0..15  -> 4 cols each
    int ty = tid >> 4;        // 0..15  -> 4 rows each
    int row0 = blockIdx.y * BM;
    int col0 = blockIdx.x * BN;

    // A-tile load indices: 64 rows x 16 k, float4 along K
    int ar = tid >> 2;          // 0..63
    int ac = (tid & 3) * 4;     // 0,4,8,12
    // B-tile load indices: 16 k x 64 cols, float4 along N
    int br = tid >> 4;          // 0..15
    int bc = (tid & 15) * 4;    // 0..60

    float acc[4][4] = {};

    for (int k0 = 0; k0 < K; k0 += BK) {
        float4 av = make_float4(0.f, 0.f, 0.f, 0.f);
        if (row0 + ar < M)
            av = *(const float4*)&A[(size_t)(row0 + ar) * K + k0 + ac];
        As[ac + 0][ar] = av.x;
        As[ac + 1][ar] = av.y;
        As[ac + 2][ar] = av.z;
        As[ac + 3][ar] = av.w;

        float4 bv = *(const float4*)&B[(size_t)(k0 + br) * N + col0 + bc];
        *(float4*)&Bs[br][bc] = bv;
        __syncthreads();

#pragma unroll
        for (int k = 0; k < BK; k++) {
            float a[4], b[4];
            *(float4*)a = *(const float4*)&As[k][ty * 4];
            *(float4*)b = *(const float4*)&Bs[k][tx * 4];
#pragma unroll
            for (int i = 0; i < 4; i++)
#pragma unroll
                for (int j = 0; j < 4; j++)
                    acc[i][j] += a[i] * b[j];
        }
        __syncthreads();
    }

#pragma unroll
    for (int i = 0; i < 4; i++) {
        int m = row0 + ty * 4 + i;
        if (m < M) {
            float4 o;
            int cb = col0 + tx * 4;
            o.x = acc[i][0] + bias[cb + 0];
            o.y = acc[i][1] + bias[cb + 1];
            o.z = acc[i][2] + bias[cb + 2];
            o.w = acc[i][3] + bias[cb + 3];
            *(float4*)&C[(size_t)m * N + cb] = o;
        }
    }
}

// ---------------- per-dst-node GATv2 aggregation ----------------
// One block (128 threads) per destination node. No atomics.
// Pass 1: per-edge logits (cooperative dot with att), stored in shared.
// Softmax per head in shared. Pass 2: alpha-weighted accumulation of xl[src].
template <int H, int C, bool DO_ELU>
__global__ void __launch_bounds__(128)
k_gat_aggregate(const float* __restrict__ ew,
                const int*   __restrict__ srcArr,
                const float* __restrict__ We,
                const float* __restrict__ att,
                const float* __restrict__ bias,
                float* __restrict__ out) {
    constexpr int HC  = H * C;
    constexpr int T   = 128;
    constexpr int VPT = HC / T;       // 4 (H=4,C=128) or 2 (H=1,C=256)
    constexpr int MAXDEG = 1024;

    __shared__ float sh_xr[HC];
    __shared__ float sh_We[HC];
    __shared__ float sh_att[HC];
    __shared__ float sh_l[MAXDEG * H];
    __shared__ float sh_red[4];

    const int nd  = blockIdx.x;
    const int tid = threadIdx.x;
    const int chb = tid * VPT;            // base channel of this thread
    const int h   = chb / C;              // head of this thread

    // stage per-node / per-layer constants
    for (int i = tid; i < HC; i += T) {
        sh_xr[i]  = g_XR[(size_t)nd * HC + i];
        sh_We[i]  = We[i];
        sh_att[i] = att[i];
    }
    __syncthreads();

    int s0  = g_start[nd];
    int deg = g_start[nd + 1] - s0;
    if (deg > MAXDEG) deg = MAXDEG;   // unreachable for this dataset (max deg ~ 35)

    // ---- pass 1: logits ----
    for (int eo = 0; eo < deg; eo++) {
        int   e = g_csr[s0 + eo];
        int   s = srcArr[e];
        float w = ew[e];
        const float* xlrow = &g_XL[(size_t)s * HC + chb];

        float xv[VPT];
        if constexpr (VPT == 4) {
            float4 v = *(const float4*)xlrow;
            xv[0] = v.x; xv[1] = v.y; xv[2] = v.z; xv[3] = v.w;
        } else {
            float2 v = *(const float2*)xlrow;
            xv[0] = v.x; xv[1] = v.y;
        }

        float partial = 0.f;
#pragma unroll
        for (int j = 0; j < VPT; j++) {
            float v = xv[j] + sh_xr[chb + j] + w * sh_We[chb + j];
            v = (v > 0.f) ? v : 0.2f * v;   // leaky_relu(0.2)
            partial += v * sh_att[chb + j];
        }
        // warp reduce
#pragma unroll
        for (int off = 16; off; off >>= 1)
            partial += __shfl_xor_sync(0xffffffff, partial, off);

        if constexpr (H == 4) {
            // one warp == one head
            if ((tid & 31) == 0) sh_l[eo * H + h] = partial;
        } else {
            // whole block == one head: combine 4 warp partials
            if ((tid & 31) == 0) sh_red[tid >> 5] = partial;
            __syncthreads();
            if (tid == 0) sh_l[eo] = sh_red[0] + sh_red[1] + sh_red[2] + sh_red[3];
            __syncthreads();
        }
    }
    __syncthreads();

    // ---- softmax per head (deg is small, ~12 on average) ----
    if (tid < H) {
        float m = -INFINITY;
        for (int eo = 0; eo < deg; eo++) m = fmaxf(m, sh_l[eo * H + tid]);
        float ssum = 0.f;
        for (int eo = 0; eo < deg; eo++) {
            float p = expf(sh_l[eo * H + tid] - m);
            sh_l[eo * H + tid] = p;
            ssum += p;
        }
        float inv = 1.f / (ssum + 1e-16f);
        for (int eo = 0; eo < deg; eo++) sh_l[eo * H + tid] *= inv;
    }
    __syncthreads();

    // ---- pass 2: weighted accumulation ----
    float acc[VPT] = {};
    for (int eo = 0; eo < deg; eo++) {
        int   e = g_csr[s0 + eo];
        int   s = srcArr[e];
        float a = sh_l[eo * H + h];
        const float* xlrow = &g_XL[(size_t)s * HC + chb];
        if constexpr (VPT == 4) {
            float4 v = *(const float4*)xlrow;
            acc[0] += a * v.x; acc[1] += a * v.y; acc[2] += a * v.z; acc[3] += a * v.w;
        } else {
            float2 v = *(const float2*)xlrow;
            acc[0] += a * v.x; acc[1] += a * v.y;
        }
    }

    // ---- epilogue: + bias, optional ELU ----
#pragma unroll
    for (int j = 0; j < VPT; j++) {
        float o = acc[j] + bias[chb + j];
        if constexpr (DO_ELU) o = (o > 0.f) ? o : expm1f(o);
        out[(size_t)nd * HC + chb + j] = o;
    }
}

// ---------------- launch ----------------
extern "C" void kernel_launch(void* const* d_in, const int* in_sizes, int n_in,
                              void* d_out, int out_size) {
    const float* x   = (const float*)d_in[0];
    const int*   ei  = (const int*)  d_in[1];
    const float* ew  = (const float*)d_in[2];
    const int* src = ei;
    const int* dst = ei + NE;

    const float *Wl[3], *bl[3], *Wr[3], *br[3], *We[3], *att[3], *bias[3];
    for (int l = 0; l < 3; l++) {
        int b = 3 + 7 * l;
        Wl[l]   = (const float*)d_in[b + 0];
        bl[l]   = (const float*)d_in[b + 1];
        Wr[l]   = (const float*)d_in[b + 2];
        br[l]   = (const float*)d_in[b + 3];
        We[l]   = (const float*)d_in[b + 4];
        att[l]  = (const float*)d_in[b + 5];
        bias[l] = (const float*)d_in[b + 6];
    }

    float *dXL, *dXR, *dH;
    cudaGetSymbolAddress((void**)&dXL, g_XL);
    cudaGetSymbolAddress((void**)&dXR, g_XR);
    cudaGetSymbolAddress((void**)&dH,  g_H);
    float* dOut = (float*)d_out;

    // CSR by destination
    k_zero_deg<<<(NT + 255) / 256, 256>>>();
    k_hist    <<<(NE + 255) / 256, 256>>>(dst);
    k_scan    <<<1, 256>>>();
    k_scatter <<<(NE + 255) / 256, 256>>>(dst);

    const int MB = (NT + 63) / 64;   // 157 row tiles

    // ---- layer 0: in 64 -> 4x128 ----
    k_gemm_dual<<<dim3(512 / 64, MB, 2), 256>>>(x,
        Wl[0], bl[0], dXL,  Wr[0], br[0], dXR, NT, 512, 64);
    k_gat_aggregate<4, 128, true><<<NT, 128>>>(ew, src, We[0], att[0], bias[0], dH);

    // ---- layer 1: 512 -> 4x128 ----
    k_gemm_dual<<<dim3(512 / 64, MB, 2), 256>>>(dH,
        Wl[1], bl[1], dXL,  Wr[1], br[1], dXR, NT, 512, 512);
    k_gat_aggregate<4, 128, true><<<NT, 128>>>(ew, src, We[1], att[1], bias[1], dH);

    // ---- layer 2: 512 -> 1x256 (no ELU), writes d_out directly ----
    k_gemm_dual<<<dim3(256 / 64, MB, 2), 256>>>(dH,
        Wl[2], bl[2], dXL,  Wr[2], br[2], dXR, NT, 256, 512);
    k_gat_aggregate<1, 256, false><<<NT, 128>>>(ew, src, We[2], att[2], bias[2], dOut);
}